// round 3
// baseline (speedup 1.0000x reference)
#include <cuda_runtime.h>
#include <cuda_bf16.h>

#define NLEV  256
#define NBINS 2048

// lut[b] = count(u < fmaf(b-1, w, lo)) : one-bin-conservative seed (never overcounts)
__device__ __align__(16) short g_lut[NBINS];

__global__ void build_lut_kernel(const float* __restrict__ u)
{
    int b = blockIdx.x * blockDim.x + threadIdx.x;   // 0..NBINS-1
    if (b >= NBINS) return;
    float lo = u[0];
    float hi = u[NLEV - 1];
    float w  = (hi - lo) * (1.0f / NBINS);
    float bs = fmaf((float)(b - 1), w, lo);          // one bin of safety margin

    int pos = 0;                                     // count(u < bs), branchless
    #pragma unroll
    for (int s = 128; s >= 1; s >>= 1) {
        if (u[pos + s - 1] < bs) pos += s;
    }
    g_lut[b] = (short)pos;
}

__global__ void __launch_bounds__(256, 6)
agc_quant_kernel(const float4* __restrict__ in4,
                 const float4* __restrict__ mn4,
                 const float*  __restrict__ uvals,
                 float* __restrict__ out_dq,   // d_out[0 .. n)
                 float* __restrict__ out_sym,  // d_out[n .. 2n)
                 int n4, int n)
{
    __shared__ float us[NLEV * 32];              // 32 KB, replicated: us[idx*32+lane]
    __shared__ __align__(16) short slut[NBINS];  // 4 KB seed LUT

    const int tid  = threadIdx.x;
    const int lane = tid & 31;

    for (int i = tid; i < NLEV * 32; i += blockDim.x)
        us[i] = uvals[i >> 5];
    {
        const int4* src = reinterpret_cast<const int4*>(g_lut);
        int4*       dst = reinterpret_cast<int4*>(slut);
        for (int i = tid; i < NBINS * (int)sizeof(short) / 16; i += blockDim.x)
            dst[i] = src[i];
    }
    __syncthreads();

    const float lo    = us[0 * 32 + lane];       // lane's own copy (broadcast-equal)
    const float hi    = us[(NLEV - 1) * 32 + lane];
    const float inv_w = (float)NBINS / (hi - lo);

    const int stride = gridDim.x * blockDim.x;

    for (int i = blockIdx.x * blockDim.x + tid; i < n4; i += stride) {
        float4 x = in4[i];
        float4 m = mn4[i];

        float v[4];
        v[0] = x.x - m.x; v[1] = x.y - m.y; v[2] = x.z - m.z; v[3] = x.w - m.w;

        // Seed from conservative LUT: 4 independent LDS in flight.
        int p[4];
        #pragma unroll
        for (int j = 0; j < 4; j++) {
            int b = (int)((v[j] - lo) * inv_w);
            b = b < 0 ? 0 : (b > NBINS - 1 ? NBINS - 1 : b);
            p[j] = slut[b];
        }

        // Forward scan to exact count(u < v). Expected ~0.25 iters/elem,
        // conflict-free via replicated codebook.
        #pragma unroll
        for (int j = 0; j < 4; j++) {
            int q = p[j];
            while (q < NLEV && us[(q << 5) + lane] < v[j]) ++q;
            p[j] = q;
        }

        float dq[4], sy[4];
        #pragma unroll
        for (int j = 0; j < 4; j++) {
            int c = p[j];
            c = c < 1 ? 1 : (c > NLEV - 1 ? NLEV - 1 : c);
            float left  = us[((c - 1) << 5) + lane];
            float right = us[(c << 5) + lane];
            bool tl = fabsf(v[j] - left) <= fabsf(v[j] - right);
            sy[j] = (float)(tl ? c - 1 : c);
            dq[j] = tl ? left : right;
        }
        dq[0] += m.x; dq[1] += m.y; dq[2] += m.z; dq[3] += m.w;

        reinterpret_cast<float4*>(out_dq)[i]  = make_float4(dq[0], dq[1], dq[2], dq[3]);
        reinterpret_cast<float4*>(out_sym)[i] = make_float4(sy[0], sy[1], sy[2], sy[3]);
    }

    // Scalar tail — block 0 only.
    if (blockIdx.x == 0) {
        const float* in1 = reinterpret_cast<const float*>(in4);
        const float* mn1 = reinterpret_cast<const float*>(mn4);
        for (int i = n4 * 4 + tid; i < n; i += blockDim.x) {
            float vv = in1[i] - mn1[i];
            int b = (int)((vv - lo) * inv_w);
            b = b < 0 ? 0 : (b > NBINS - 1 ? NBINS - 1 : b);
            int q = slut[b];
            while (q < NLEV && us[(q << 5) + lane] < vv) ++q;
            int c = q < 1 ? 1 : (q > NLEV - 1 ? NLEV - 1 : q);
            float left  = us[((c - 1) << 5) + lane];
            float right = us[(c << 5) + lane];
            bool tl = fabsf(vv - left) <= fabsf(vv - right);
            out_sym[i] = (float)(tl ? c - 1 : c);
            out_dq[i]  = (tl ? left : right) + mn1[i];
        }
    }
}

extern "C" void kernel_launch(void* const* d_in, const int* in_sizes, int n_in,
                              void* d_out, int out_size)
{
    const float* inputs = (const float*)d_in[0];
    const float* means  = (const float*)d_in[1];
    const float* uvals  = (const float*)d_in[2];
    float* out = (float*)d_out;

    const int n  = out_size / 2;
    const int n4 = n / 4;

    float* out_dq  = out;
    float* out_sym = out + n;

    build_lut_kernel<<<NBINS / 256, 256>>>(uvals);

    const int threads = 256;
    int blocks = 888;                        // 6 CTAs/SM on 148 SMs
    int maxb = (n4 + threads - 1) / threads;
    if (blocks > maxb && maxb > 0) blocks = maxb;
    if (blocks < 1) blocks = 1;

    agc_quant_kernel<<<blocks, threads>>>(
        (const float4*)inputs, (const float4*)means, uvals,
        out_dq, out_sym, n4, n);
}

// round 4
// speedup vs baseline: 1.0309x; 1.0309x over previous
#include <cuda_runtime.h>
#include <cuda_bf16.h>

#define NLEV  256
#define NBINS 2048
#define VPT   4     // float4 per stream per thread => 16 elements/thread

// lut[b] = count(u < fmaf(b-1, w, lo)) : one-bin-conservative seed (never overcounts)
__device__ __align__(16) short g_lut[NBINS];

__global__ void build_lut_kernel(const float* __restrict__ u)
{
    int b = blockIdx.x * blockDim.x + threadIdx.x;
    if (b >= NBINS) return;
    float lo = u[0];
    float hi = u[NLEV - 1];
    float w  = (hi - lo) * (1.0f / NBINS);
    float bs = fmaf((float)(b - 1), w, lo);

    int pos = 0;
    #pragma unroll
    for (int s = 128; s >= 1; s >>= 1) {
        if (u[pos + s - 1] < bs) pos += s;
    }
    g_lut[b] = (short)pos;
}

__global__ void __launch_bounds__(256, 3)
agc_quant_kernel(const float4* __restrict__ in4,
                 const float4* __restrict__ mn4,
                 const float*  __restrict__ uvals,
                 float* __restrict__ out_dq,
                 float* __restrict__ out_sym,
                 int n4, int n)
{
    __shared__ float us[NLEV * 32];              // replicated: us[idx*32+lane]
    __shared__ __align__(16) short slut[NBINS];

    const int tid  = threadIdx.x;
    const int lane = tid & 31;

    for (int i = tid; i < NLEV * 32; i += blockDim.x)
        us[i] = uvals[i >> 5];
    {
        const int4* src = reinterpret_cast<const int4*>(g_lut);
        int4*       dst = reinterpret_cast<int4*>(slut);
        for (int i = tid; i < NBINS * (int)sizeof(short) / 16; i += blockDim.x)
            dst[i] = src[i];
    }
    __syncthreads();

    const float lo    = us[lane];
    const float hi    = us[((NLEV - 1) << 5) + lane];
    const float inv_w = (float)NBINS / (hi - lo);

    const int bdim   = blockDim.x;                 // 256
    const int tile   = bdim * VPT;                 // float4 per block-iter
    const int gstep  = gridDim.x * tile;

    for (int base = blockIdx.x * tile + tid; base < n4; base += gstep) {

        if (base + (VPT - 1) * bdim < n4) {
            // ---------- fast path: 8 LDG.128 issued up front ----------
            float4 x[VPT], mm[VPT];
            #pragma unroll
            for (int j = 0; j < VPT; j++) x[j]  = in4[base + j * bdim];
            #pragma unroll
            for (int j = 0; j < VPT; j++) mm[j] = mn4[base + j * bdim];

            float v[4 * VPT];
            #pragma unroll
            for (int j = 0; j < VPT; j++) {
                v[4*j+0] = x[j].x - mm[j].x;
                v[4*j+1] = x[j].y - mm[j].y;
                v[4*j+2] = x[j].z - mm[j].z;
                v[4*j+3] = x[j].w - mm[j].w;
            }

            // seed all 16 searches (independent LDS in flight)
            int p[4 * VPT];
            #pragma unroll
            for (int e = 0; e < 4 * VPT; e++) {
                int b = (int)((v[e] - lo) * inv_w);
                b = b < 0 ? 0 : (b > NBINS - 1 ? NBINS - 1 : b);
                p[e] = slut[b];
            }
            // exact count(u < v): conflict-free forward scan
            #pragma unroll
            for (int e = 0; e < 4 * VPT; e++) {
                int q = p[e];
                while (q < NLEV && us[(q << 5) + lane] < v[e]) ++q;
                p[e] = q;
            }

            float dq[4 * VPT], sy[4 * VPT];
            #pragma unroll
            for (int e = 0; e < 4 * VPT; e++) {
                int c = p[e];
                c = c < 1 ? 1 : (c > NLEV - 1 ? NLEV - 1 : c);
                float left  = us[((c - 1) << 5) + lane];
                float right = us[(c << 5) + lane];
                bool tl = fabsf(v[e] - left) <= fabsf(v[e] - right);
                sy[e] = (float)(tl ? c - 1 : c);
                dq[e] = tl ? left : right;
            }
            #pragma unroll
            for (int j = 0; j < VPT; j++) {
                reinterpret_cast<float4*>(out_dq)[base + j * bdim] =
                    make_float4(dq[4*j+0] + mm[j].x, dq[4*j+1] + mm[j].y,
                                dq[4*j+2] + mm[j].z, dq[4*j+3] + mm[j].w);
                reinterpret_cast<float4*>(out_sym)[base + j * bdim] =
                    make_float4(sy[4*j+0], sy[4*j+1], sy[4*j+2], sy[4*j+3]);
            }
        } else {
            // ---------- guarded path ----------
            #pragma unroll
            for (int j = 0; j < VPT; j++) {
                int i = base + j * bdim;
                if (i >= n4) break;
                float4 x = in4[i];
                float4 m = mn4[i];
                float vv[4] = { x.x - m.x, x.y - m.y, x.z - m.z, x.w - m.w };
                float dq[4], sy[4];
                #pragma unroll
                for (int k = 0; k < 4; k++) {
                    int b = (int)((vv[k] - lo) * inv_w);
                    b = b < 0 ? 0 : (b > NBINS - 1 ? NBINS - 1 : b);
                    int q = slut[b];
                    while (q < NLEV && us[(q << 5) + lane] < vv[k]) ++q;
                    int c = q < 1 ? 1 : (q > NLEV - 1 ? NLEV - 1 : q);
                    float left  = us[((c - 1) << 5) + lane];
                    float right = us[(c << 5) + lane];
                    bool tl = fabsf(vv[k] - left) <= fabsf(vv[k] - right);
                    sy[k] = (float)(tl ? c - 1 : c);
                    dq[k] = tl ? left : right;
                }
                reinterpret_cast<float4*>(out_dq)[i] =
                    make_float4(dq[0] + m.x, dq[1] + m.y, dq[2] + m.z, dq[3] + m.w);
                reinterpret_cast<float4*>(out_sym)[i] =
                    make_float4(sy[0], sy[1], sy[2], sy[3]);
            }
        }
    }

    // Scalar float tail (n % 4 != 0) — block 0 only.
    if (blockIdx.x == 0) {
        const float* in1 = reinterpret_cast<const float*>(in4);
        const float* mn1 = reinterpret_cast<const float*>(mn4);
        for (int i = n4 * 4 + tid; i < n; i += blockDim.x) {
            float vv = in1[i] - mn1[i];
            int b = (int)((vv - lo) * inv_w);
            b = b < 0 ? 0 : (b > NBINS - 1 ? NBINS - 1 : b);
            int q = slut[b];
            while (q < NLEV && us[(q << 5) + lane] < vv) ++q;
            int c = q < 1 ? 1 : (q > NLEV - 1 ? NLEV - 1 : q);
            float left  = us[((c - 1) << 5) + lane];
            float right = us[(c << 5) + lane];
            bool tl = fabsf(vv - left) <= fabsf(vv - right);
            out_sym[i] = (float)(tl ? c - 1 : c);
            out_dq[i]  = (tl ? left : right) + mn1[i];
        }
    }
}

extern "C" void kernel_launch(void* const* d_in, const int* in_sizes, int n_in,
                              void* d_out, int out_size)
{
    const float* inputs = (const float*)d_in[0];
    const float* means  = (const float*)d_in[1];
    const float* uvals  = (const float*)d_in[2];
    float* out = (float*)d_out;

    const int n  = out_size / 2;
    const int n4 = n / 4;

    float* out_dq  = out;
    float* out_sym = out + n;

    build_lut_kernel<<<NBINS / 256, 256>>>(uvals);

    const int threads = 256;
    // occupancy 3 CTAs/SM on 148 SMs -> one resident wave of 444, grid-stride
    int blocks = 444;
    int maxb = (n4 + threads * VPT - 1) / (threads * VPT);
    if (blocks > maxb && maxb > 0) blocks = maxb;
    if (blocks < 1) blocks = 1;

    agc_quant_kernel<<<blocks, threads>>>(
        (const float4*)inputs, (const float4*)means, uvals,
        out_dq, out_sym, n4, n);
}

// round 5
// speedup vs baseline: 1.1414x; 1.1072x over previous
#include <cuda_runtime.h>
#include <cuda_bf16.h>

#define NLEV  256
#define NBINS 2048
#define VPT   2     // float4 per stream per thread => 8 elements/thread

__global__ void __launch_bounds__(256, 5)
agc_quant_kernel(const float4* __restrict__ in4,
                 const float4* __restrict__ mn4,
                 const float*  __restrict__ uvals,
                 float* __restrict__ out_dq,
                 float* __restrict__ out_sym,
                 int n4, int n)
{
    __shared__ float us[NLEV * 32];              // 32 KB, replicated: us[idx*32+lane]
    __shared__ __align__(16) short slut[NBINS];  // 4 KB conservative seed LUT

    const int tid  = threadIdx.x;
    const int lane = tid & 31;

    // 1) replicated codebook (uvals is L2/L1-hot after first CTA)
    for (int i = tid; i < NLEV * 32; i += blockDim.x)
        us[i] = uvals[i >> 5];
    __syncthreads();

    const float lo    = us[lane];
    const float hi    = us[((NLEV - 1) << 5) + lane];
    const float w     = (hi - lo) * (1.0f / NBINS);
    const float inv_w = (float)NBINS / (hi - lo);

    // 2) in-CTA LUT build: slut[b] = count(u < binstart(b-1))  (never overcounts)
    for (int b = tid; b < NBINS; b += blockDim.x) {
        float bs = fmaf((float)(b - 1), w, lo);   // one-bin safety margin
        int pos = 0;
        #pragma unroll
        for (int s = 128; s >= 1; s >>= 1) {
            if (us[((pos + s - 1) << 5) + lane] < bs) pos += s;
        }
        slut[b] = (short)pos;
    }
    __syncthreads();

    const int bdim  = blockDim.x;                 // 256
    const int tile  = bdim * VPT;
    const int gstep = gridDim.x * tile;

    for (int base = blockIdx.x * tile + tid; base < n4; base += gstep) {

        if (base + (VPT - 1) * bdim < n4) {
            // fast path: 4 LDG.128 front-batched
            float4 x[VPT], mm[VPT];
            #pragma unroll
            for (int j = 0; j < VPT; j++) x[j]  = __ldcs(&in4[base + j * bdim]);
            #pragma unroll
            for (int j = 0; j < VPT; j++) mm[j] = __ldcs(&mn4[base + j * bdim]);

            float v[4 * VPT];
            #pragma unroll
            for (int j = 0; j < VPT; j++) {
                v[4*j+0] = x[j].x - mm[j].x;
                v[4*j+1] = x[j].y - mm[j].y;
                v[4*j+2] = x[j].z - mm[j].z;
                v[4*j+3] = x[j].w - mm[j].w;
            }

            int p[4 * VPT];
            #pragma unroll
            for (int e = 0; e < 4 * VPT; e++) {
                int b = (int)((v[e] - lo) * inv_w);
                b = b < 0 ? 0 : (b > NBINS - 1 ? NBINS - 1 : b);
                p[e] = slut[b];
            }
            #pragma unroll
            for (int e = 0; e < 4 * VPT; e++) {
                int q = p[e];
                while (q < NLEV && us[(q << 5) + lane] < v[e]) ++q;  // exact count(u<v)
                p[e] = q;
            }

            float dq[4 * VPT], sy[4 * VPT];
            #pragma unroll
            for (int e = 0; e < 4 * VPT; e++) {
                int c = p[e];
                c = c < 1 ? 1 : (c > NLEV - 1 ? NLEV - 1 : c);
                float left  = us[((c - 1) << 5) + lane];
                float right = us[(c << 5) + lane];
                bool tl = fabsf(v[e] - left) <= fabsf(v[e] - right);
                sy[e] = (float)(tl ? c - 1 : c);
                dq[e] = tl ? left : right;
            }
            #pragma unroll
            for (int j = 0; j < VPT; j++) {
                __stcs(&reinterpret_cast<float4*>(out_dq)[base + j * bdim],
                       make_float4(dq[4*j+0] + mm[j].x, dq[4*j+1] + mm[j].y,
                                   dq[4*j+2] + mm[j].z, dq[4*j+3] + mm[j].w));
                __stcs(&reinterpret_cast<float4*>(out_sym)[base + j * bdim],
                       make_float4(sy[4*j+0], sy[4*j+1], sy[4*j+2], sy[4*j+3]));
            }
        } else {
            #pragma unroll
            for (int j = 0; j < VPT; j++) {
                int i = base + j * bdim;
                if (i >= n4) break;
                float4 x = in4[i];
                float4 m = mn4[i];
                float vv[4] = { x.x - m.x, x.y - m.y, x.z - m.z, x.w - m.w };
                float dq[4], sy[4];
                #pragma unroll
                for (int k = 0; k < 4; k++) {
                    int b = (int)((vv[k] - lo) * inv_w);
                    b = b < 0 ? 0 : (b > NBINS - 1 ? NBINS - 1 : b);
                    int q = slut[b];
                    while (q < NLEV && us[(q << 5) + lane] < vv[k]) ++q;
                    int c = q < 1 ? 1 : (q > NLEV - 1 ? NLEV - 1 : q);
                    float left  = us[((c - 1) << 5) + lane];
                    float right = us[(c << 5) + lane];
                    bool tl = fabsf(vv[k] - left) <= fabsf(vv[k] - right);
                    sy[k] = (float)(tl ? c - 1 : c);
                    dq[k] = tl ? left : right;
                }
                reinterpret_cast<float4*>(out_dq)[i] =
                    make_float4(dq[0] + m.x, dq[1] + m.y, dq[2] + m.z, dq[3] + m.w);
                reinterpret_cast<float4*>(out_sym)[i] =
                    make_float4(sy[0], sy[1], sy[2], sy[3]);
            }
        }
    }

    // Scalar float tail (n % 4 != 0) — block 0 only.
    if (blockIdx.x == 0) {
        const float* in1 = reinterpret_cast<const float*>(in4);
        const float* mn1 = reinterpret_cast<const float*>(mn4);
        for (int i = n4 * 4 + tid; i < n; i += blockDim.x) {
            float vv = in1[i] - mn1[i];
            int b = (int)((vv - lo) * inv_w);
            b = b < 0 ? 0 : (b > NBINS - 1 ? NBINS - 1 : b);
            int q = slut[b];
            while (q < NLEV && us[(q << 5) + lane] < vv) ++q;
            int c = q < 1 ? 1 : (q > NLEV - 1 ? NLEV - 1 : q);
            float left  = us[((c - 1) << 5) + lane];
            float right = us[(c << 5) + lane];
            bool tl = fabsf(vv - left) <= fabsf(vv - right);
            out_sym[i] = (float)(tl ? c - 1 : c);
            out_dq[i]  = (tl ? left : right) + mn1[i];
        }
    }
}

extern "C" void kernel_launch(void* const* d_in, const int* in_sizes, int n_in,
                              void* d_out, int out_size)
{
    const float* inputs = (const float*)d_in[0];
    const float* means  = (const float*)d_in[1];
    const float* uvals  = (const float*)d_in[2];
    float* out = (float*)d_out;

    const int n  = out_size / 2;
    const int n4 = n / 4;

    float* out_dq  = out;
    float* out_sym = out + n;

    const int threads = 256;
    int blocks = 740;                        // 5 CTAs/SM on 148 SMs, grid-stride
    int maxb = (n4 + threads * VPT - 1) / (threads * VPT);
    if (blocks > maxb && maxb > 0) blocks = maxb;
    if (blocks < 1) blocks = 1;

    agc_quant_kernel<<<blocks, threads>>>(
        (const float4*)inputs, (const float4*)means, uvals,
        out_dq, out_sym, n4, n);
}